// round 6
// baseline (speedup 1.0000x reference)
#include <cuda_runtime.h>
#include <math.h>

#define TPB 128
#define ROWS_PER_BLOCK 256

// ---------------- constant bank ----------------
// [0    : 4800)  emb cols 12..31  [j*20 + (c-12)]
// [4800 : 5040)  kbc [j] = bc[j] + 2*C
#define EMBC_OFF 0
#define KBC_OFF  4800
#define CTAB_N   5040
__constant__ __align__(16) float c_tab[CTAB_N];
__device__ __align__(16) float g_stage[CTAB_N];
__device__ __align__(16) float g_roots[240 * 8];
__device__ __align__(16) float g_embG[240 * 24];   // emb cols 32..55 (incl. base ctrl)

typedef unsigned long long u64;

__device__ __forceinline__ u64 pk(float x, float y) {
    u64 r; asm("mov.b64 %0,{%1,%2};" : "=l"(r) : "f"(x), "f"(y)); return r;
}
__device__ __forceinline__ void upk(float& x, float& y, u64 v) {
    asm("mov.b64 {%0,%1},%2;" : "=f"(x), "=f"(y) : "l"(v));
}
__device__ __forceinline__ u64 f2fma(u64 a, u64 b, u64 c) {
    u64 d; asm("fma.rn.f32x2 %0,%1,%2,%3;" : "=l"(d) : "l"(a), "l"(b), "l"(c)); return d;
}
__device__ __forceinline__ u64 f2mul(u64 a, u64 b) {
    u64 d; asm("mul.rn.f32x2 %0,%1,%2;" : "=l"(d) : "l"(a), "l"(b)); return d;
}
__device__ __forceinline__ u64 f2add(u64 a, u64 b) {
    u64 d; asm("add.rn.f32x2 %0,%1,%2;" : "=l"(d) : "l"(a), "l"(b)); return d;
}
__device__ __forceinline__ float ex2a(float x) {
    float y; asm("ex2.approx.ftz.f32 %0,%1;" : "=f"(y) : "f"(x)); return y;
}

// Combined prep: roots + constant-bank stage + global emb slice.
__global__ void prep_kernel(const float* __restrict__ le,
                            const float* __restrict__ bctl,
                            const float* __restrict__ bc) {
    const float C = 1.0201941611100342f;   // log2(e)/sqrt(2)
    int i = blockIdx.x * blockDim.x + threadIdx.x;
    if (i < 240) {
        float v[8];
#pragma unroll
        for (int k = 0; k < 8; k++) v[k] = 0.f;
        if (i < 112) {
            int p = i >> 2, sb = i & 3;
            int a = 0, rem = p;
            while (rem >= 7 - a) { rem -= (7 - a); a++; }
            int b = a + 1 + rem;
            v[a] = (sb & 2) ? -1.f : 1.f;
            v[b] = (sb & 1) ? -1.f : 1.f;
        } else {
            int b = (i - 112) << 1;
            if (__popc(b) & 1) b |= 1;
#pragma unroll
            for (int k = 0; k < 8; k++) v[k] = ((b >> k) & 1) ? -0.5f : 0.5f;
        }
#pragma unroll
        for (int k = 0; k < 8; k++) g_roots[i * 8 + k] = v[k];
    }
    if (i < CTAB_N) {
        float v;
        if (i < KBC_OFF) { int j = i / 20, c = i - j * 20 + 12; v = le[j * 52 + c]; }
        else             { v = bc[i - KBC_OFF] + 2.0f * C; }
        g_stage[i] = v;
    }
    if (i < 240 * 24) {
        int j = i / 24, c = i - j * 24 + 32;
        g_embG[i] = (c < 52) ? le[j * 52 + c] : bctl[j * 4 + (c - 52)];
    }
}

__device__ __forceinline__ float gelu_exact(float x) {
    return 0.5f * x * (1.0f + erff(x * 0.70710678118654752f));
}

// Analytic nearest-E8-root: returns reference enumeration index, subtracts root*s in place.
__device__ __forceinline__ int decode_step(float res[8], float s) {
    float a[8];
#pragma unroll
    for (int k = 0; k < 8; k++) a[k] = fabsf(res[k]);
    int m1 = 0; float v1 = a[0];
#pragma unroll
    for (int k = 1; k < 8; k++) if (a[k] > v1) { v1 = a[k]; m1 = k; }
    int m2 = -1; float v2 = -1.f;
#pragma unroll
    for (int k = 0; k < 8; k++) if (k != m1 && a[k] > v2) { v2 = a[k]; m2 = k; }
    float valA = v1 + v2;
    float sum = 0.f;
#pragma unroll
    for (int k = 0; k < 8; k++) sum += a[k];
    int mask = 0;
#pragma unroll
    for (int k = 0; k < 8; k++) mask |= (res[k] < 0.f) ? (1 << k) : 0;
    int km = 0; float vm = a[0];
#pragma unroll
    for (int k = 1; k < 8; k++) if (a[k] < vm) { vm = a[k]; km = k; }
    int par = __popc(mask) & 1;
    float valB = 0.5f * sum - (par ? vm : 0.f);
    int idx;
    if (valA >= valB) {            // tie -> type A (lower enumeration index)
        int i = (m1 < m2) ? m1 : m2, jj = (m1 < m2) ? m2 : m1;
        int bi = (res[i] < 0.f) ? 1 : 0, bj = (res[jj] < 0.f) ? 1 : 0;
        idx = (7 * i - (i * (i - 1)) / 2 + (jj - i - 1)) * 4 + bi * 2 + bj;
        float di = bi ? -s : s, dj = bj ? -s : s;
#pragma unroll
        for (int k = 0; k < 8; k++) {
            if (k == i)  res[k] -= di;
            if (k == jj) res[k] -= dj;
        }
    } else {
        int bits = par ? (mask ^ (1 << km)) : mask;
        idx = 112 + (bits >> 1);
        float hs = 0.5f * s;
#pragma unroll
        for (int k = 0; k < 8; k++) res[k] -= ((bits >> k) & 1) ? -hs : hs;
    }
    return idx;
}

// Gated refine MLP for one row (acc[28] u64 = 56 floats, cols 0..51 refined).
__device__ __forceinline__ void refine_row(u64 acc[28],
                                           const float* __restrict__ rw1,
                                           const float* rw2TS, const float* rb1S,
                                           const float* rb2S, u64 gateb) {
    u64 r2a[26];
#pragma unroll
    for (int k = 0; k < 26; k++) r2a[k] = 0ull;
#pragma unroll 2
    for (int c = 0; c < 52; c++) {
        u64 p = pk(rb1S[c], 0.f);
        const ulonglong2* wr = reinterpret_cast<const ulonglong2*>(rw1 + c * 52);
#pragma unroll
        for (int k = 0; k < 13; k++) {
            ulonglong2 w = __ldg(&wr[k]);
            p = f2fma(acc[2 * k], w.x, p);
            p = f2fma(acc[2 * k + 1], w.y, p);
        }
        float pl, ph; upk(pl, ph, p);
        float gv = gelu_exact(pl + ph);
        u64 gvb = pk(gv, gv);
        const ulonglong2* w2r = reinterpret_cast<const ulonglong2*>(rw2TS + c * 52);
#pragma unroll
        for (int k = 0; k < 13; k++) {
            ulonglong2 w = w2r[k];
            r2a[2 * k]     = f2fma(gvb, w.x, r2a[2 * k]);
            r2a[2 * k + 1] = f2fma(gvb, w.y, r2a[2 * k + 1]);
        }
    }
    const u64* rb2p = reinterpret_cast<const u64*>(rb2S);
#pragma unroll
    for (int k = 0; k < 26; k++)
        acc[k] = f2fma(gateb, f2add(r2a[k], rb2p[k]), acc[k]);
}

__global__ __launch_bounds__(TPB, 3) void rcpl_kernel(
    const float* __restrict__ obs,   const float* __restrict__ w1, const float* __restrict__ b1,
    const float* __restrict__ w2,    const float* __restrict__ b2,
    const float* __restrict__ le,    const float* __restrict__ rctl,
    const float* __restrict__ ld,
    const float* __restrict__ rb1,
    const float* __restrict__ rw1,
    const float* __restrict__ rw2,   const float* __restrict__ rb2,
    const float* __restrict__ rgate, float* __restrict__ out, int B)
{
    __shared__ __align__(16) float rootsS[1920];   // [j*8+k]
    __shared__ __align__(16) float embS12[2880];   // [j*12+c] emb cols 0..11
    __shared__ __align__(16) float rw2TS[2704];    // [c*52+k2] (transposed)
    __shared__ __align__(16) float w1S[448];       // [l*14+k]
    __shared__ __align__(16) float w2TS[256];      // [l*8+j]  (transposed)
    __shared__ float b1S[32];
    __shared__ float b2S[8];
    __shared__ __align__(16) float rb2S[52];
    __shared__ float rb1S[52];
    // ~33.6 KB

    const float C = 1.0201941611100342f;   // log2(e)/sqrt(2)
    const int t = threadIdx.x;

    for (int i = t; i < 1920; i += TPB) rootsS[i] = g_roots[i];
    for (int i = t; i < 2880; i += TPB) { int j = i / 12, c = i - j * 12; embS12[i] = le[j * 52 + c]; }
    for (int i = t; i < 2704; i += TPB) { int c = i / 52, k = i - c * 52; rw2TS[i] = rw2[k * 52 + c]; }
    for (int i = t; i < 448;  i += TPB) w1S[i] = w1[i];
    for (int i = t; i < 256;  i += TPB) { int l = i >> 3, j = i & 7; w2TS[i] = w2[j * 32 + l]; }
    for (int i = t; i < 32;   i += TPB) b1S[i] = b1[i];
    for (int i = t; i < 8;    i += TPB) b2S[i] = b2[i];
    for (int i = t; i < 52;   i += TPB) { rb1S[i] = rb1[i]; rb2S[i] = rb2[i]; }
    __syncthreads();

    int r0 = blockIdx.x * ROWS_PER_BLOCK + t;
    if (r0 >= B) return;
    int r1 = r0 + TPB;
    bool has1 = (r1 < B);
    int r1c = has1 ? r1 : r0;

    // ---------------- projection: 14 -> 32 -> 8 for both rows ----------------
    float x0[14], x1[14];
    {
        const float2* p0 = reinterpret_cast<const float2*>(obs + (size_t)r0 * 14);
        const float2* p1 = reinterpret_cast<const float2*>(obs + (size_t)r1c * 14);
#pragma unroll
        for (int k = 0; k < 7; k++) {
            float2 v0 = p0[k], v1 = p1[k];
            x0[2 * k] = v0.x; x0[2 * k + 1] = v0.y;
            x1[2 * k] = v1.x; x1[2 * k + 1] = v1.y;
        }
    }
    float q0[8], q1[8];
#pragma unroll
    for (int j = 0; j < 8; j++) { q0[j] = b2S[j]; q1[j] = b2S[j]; }
#pragma unroll 2
    for (int l = 0; l < 32; l++) {
        float h0 = b1S[l], h1 = b1S[l];
        const float2* wr = reinterpret_cast<const float2*>(&w1S[l * 14]);
#pragma unroll
        for (int k = 0; k < 7; k++) {
            float2 w = wr[k];
            h0 = fmaf(x0[2 * k], w.x, h0); h0 = fmaf(x0[2 * k + 1], w.y, h0);
            h1 = fmaf(x1[2 * k], w.x, h1); h1 = fmaf(x1[2 * k + 1], w.y, h1);
        }
        float g0 = gelu_exact(h0), g1 = gelu_exact(h1);
        const float4* wt = reinterpret_cast<const float4*>(&w2TS[l * 8]);
        float4 u0 = wt[0], u1 = wt[1];
        q0[0] = fmaf(g0, u0.x, q0[0]); q0[1] = fmaf(g0, u0.y, q0[1]);
        q0[2] = fmaf(g0, u0.z, q0[2]); q0[3] = fmaf(g0, u0.w, q0[3]);
        q0[4] = fmaf(g0, u1.x, q0[4]); q0[5] = fmaf(g0, u1.y, q0[5]);
        q0[6] = fmaf(g0, u1.z, q0[6]); q0[7] = fmaf(g0, u1.w, q0[7]);
        q1[0] = fmaf(g1, u0.x, q1[0]); q1[1] = fmaf(g1, u0.y, q1[1]);
        q1[2] = fmaf(g1, u0.z, q1[2]); q1[3] = fmaf(g1, u0.w, q1[3]);
        q1[4] = fmaf(g1, u1.x, q1[4]); q1[5] = fmaf(g1, u1.y, q1[5]);
        q1[6] = fmaf(g1, u1.z, q1[6]); q1[7] = fmaf(g1, u1.w, q1[7]);
    }
    {
        float n0 = 0.f, n1 = 0.f;
#pragma unroll
        for (int j = 0; j < 8; j++) { n0 = fmaf(q0[j], q0[j], n0); n1 = fmaf(q1[j], q1[j], n1); }
        float s0 = 1.4142135623730951f / fmaxf(sqrtf(n0), 1e-12f);
        float s1 = 1.4142135623730951f / fmaxf(sqrtf(n1), 1e-12f);
#pragma unroll
        for (int j = 0; j < 8; j++) { q0[j] *= s0; q1[j] *= s1; }
    }

    u64 qp0[4], qp1[4];
#pragma unroll
    for (int k = 0; k < 4; k++) { qp0[k] = pk(q0[2 * k], q0[2 * k + 1]); qp1[k] = pk(q1[2 * k], q1[2 * k + 1]); }

    // ------- fused 240-root pass: softmax-weighted table accumulate (both rows) -------
    // Port split: cols 0..11 smem | 12..31 const | 32..55 global(L1).
    u64 acc0[28], acc1[28];
#pragma unroll
    for (int k = 0; k < 28; k++) { acc0[k] = 0ull; acc1[k] = 0ull; }
    float S0 = 0.f, S1 = 0.f;
    for (int j = 0; j < 240; j++) {
        const u64* rp = reinterpret_cast<const u64*>(&rootsS[j * 8]);
        u64 rr0 = rp[0], rr1 = rp[1], rr2 = rp[2], rr3 = rp[3];
        u64 d0 = f2mul(qp0[0], rr0);
        d0 = f2fma(qp0[1], rr1, d0); d0 = f2fma(qp0[2], rr2, d0); d0 = f2fma(qp0[3], rr3, d0);
        u64 d1 = f2mul(qp1[0], rr0);
        d1 = f2fma(qp1[1], rr1, d1); d1 = f2fma(qp1[2], rr2, d1); d1 = f2fma(qp1[3], rr3, d1);
        float dl, dh; upk(dl, dh, d0); float dot0 = dl + dh;
        float el, eh; upk(el, eh, d1); float dot1 = el + eh;
        float kbc = c_tab[KBC_OFF + j];
        float e0 = ex2a(fmaf(dot0, C, -kbc));
        float e1 = ex2a(fmaf(dot1, C, -kbc));
        S0 += e0; S1 += e1;
        u64 e0b = pk(e0, e0), e1b = pk(e1, e1);
        const ulonglong2* es = reinterpret_cast<const ulonglong2*>(&embS12[j * 12]);
#pragma unroll
        for (int k = 0; k < 3; k++) {
            ulonglong2 w = es[k];
            acc0[2 * k]     = f2fma(e0b, w.x, acc0[2 * k]);
            acc0[2 * k + 1] = f2fma(e0b, w.y, acc0[2 * k + 1]);
            acc1[2 * k]     = f2fma(e1b, w.x, acc1[2 * k]);
            acc1[2 * k + 1] = f2fma(e1b, w.y, acc1[2 * k + 1]);
        }
        const ulonglong2* ec = reinterpret_cast<const ulonglong2*>(&c_tab[EMBC_OFF + j * 20]);
#pragma unroll
        for (int k = 0; k < 5; k++) {
            ulonglong2 w = ec[k];
            acc0[6 + 2 * k]     = f2fma(e0b, w.x, acc0[6 + 2 * k]);
            acc0[6 + 2 * k + 1] = f2fma(e0b, w.y, acc0[6 + 2 * k + 1]);
            acc1[6 + 2 * k]     = f2fma(e1b, w.x, acc1[6 + 2 * k]);
            acc1[6 + 2 * k + 1] = f2fma(e1b, w.y, acc1[6 + 2 * k + 1]);
        }
        const ulonglong2* eg = reinterpret_cast<const ulonglong2*>(&g_embG[j * 24]);
#pragma unroll
        for (int k = 0; k < 6; k++) {
            ulonglong2 w = __ldg(&eg[k]);
            acc0[16 + 2 * k]     = f2fma(e0b, w.x, acc0[16 + 2 * k]);
            acc0[16 + 2 * k + 1] = f2fma(e0b, w.y, acc0[16 + 2 * k + 1]);
            acc1[16 + 2 * k]     = f2fma(e1b, w.x, acc1[16 + 2 * k]);
            acc1[16 + 2 * k + 1] = f2fma(e1b, w.y, acc1[16 + 2 * k + 1]);
        }
    }
    {
        float i0 = 1.0f / S0, i1 = 1.0f / S1;
        u64 iv0 = pk(i0, i0), iv1 = pk(i1, i1);
#pragma unroll
        for (int k = 0; k < 28; k++) { acc0[k] = f2mul(acc0[k], iv0); acc1[k] = f2mul(acc1[k], iv1); }
    }

    // ------- residual E8 quantization: analytic decode fused with gathers -------
    float invd = expf(-ld[0]);
    {
        float res0[8], res1[8];
#pragma unroll
        for (int k = 0; k < 4; k++) {
            upk(res0[2 * k], res0[2 * k + 1], qp0[k]);
            upk(res1[2 * k], res1[2 * k + 1], qp1[k]);
        }
        float s = 2.f, gg = 1.f;
#pragma unroll
        for (int lev = 0; lev < 8; lev++) {
            int idx0 = decode_step(res0, s);
            int idx1 = decode_step(res1, s);
            if (lev > 0) {
                u64 gb = pk(gg, gg);
                const ulonglong2* e0p = reinterpret_cast<const ulonglong2*>(le + ((size_t)lev * 240 + idx0) * 52);
                const ulonglong2* e1p = reinterpret_cast<const ulonglong2*>(le + ((size_t)lev * 240 + idx1) * 52);
#pragma unroll
                for (int k = 0; k < 13; k++) {
                    ulonglong2 w0 = __ldg(&e0p[k]), w1v = __ldg(&e1p[k]);
                    acc0[2 * k]     = f2fma(gb, w0.x, acc0[2 * k]);
                    acc0[2 * k + 1] = f2fma(gb, w0.y, acc0[2 * k + 1]);
                    acc1[2 * k]     = f2fma(gb, w1v.x, acc1[2 * k]);
                    acc1[2 * k + 1] = f2fma(gb, w1v.y, acc1[2 * k + 1]);
                }
                ulonglong2 c0 = __ldg(reinterpret_cast<const ulonglong2*>(rctl + ((size_t)(lev - 1) * 240 + idx0) * 4));
                ulonglong2 c1 = __ldg(reinterpret_cast<const ulonglong2*>(rctl + ((size_t)(lev - 1) * 240 + idx1) * 4));
                acc0[26] = f2fma(gb, c0.x, acc0[26]); acc0[27] = f2fma(gb, c0.y, acc0[27]);
                acc1[26] = f2fma(gb, c1.x, acc1[26]); acc1[27] = f2fma(gb, c1.y, acc1[27]);
            }
            s *= invd; gg *= invd;
        }
    }

    // ------- stash row1 pre-refine acc to out (register relief), refine row0 -------
    float4* op1 = reinterpret_cast<float4*>(out + (size_t)r1c * 56);
    if (has1) {
#pragma unroll
        for (int c4 = 0; c4 < 14; c4++) {
            float4 v;
            upk(v.x, v.y, acc1[2 * c4]); upk(v.z, v.w, acc1[2 * c4 + 1]);
            op1[c4] = v;
        }
    }

    float gate = 1.0f / (1.0f + expf(-rgate[0]));
    u64 gateb = pk(gate, gate);

    refine_row(acc0, rw1, rw2TS, rb1S, rb2S, gateb);
    {
        float4* op = reinterpret_cast<float4*>(out + (size_t)r0 * 56);
#pragma unroll
        for (int c4 = 0; c4 < 14; c4++) {
            float4 v;
            upk(v.x, v.y, acc0[2 * c4]); upk(v.z, v.w, acc0[2 * c4 + 1]);
            op[c4] = v;
        }
    }

    if (has1) {
        // reload row1 acc, refine, store final
#pragma unroll
        for (int c4 = 0; c4 < 14; c4++) {
            float4 v = op1[c4];
            acc1[2 * c4] = pk(v.x, v.y); acc1[2 * c4 + 1] = pk(v.z, v.w);
        }
        refine_row(acc1, rw1, rw2TS, rb1S, rb2S, gateb);
#pragma unroll
        for (int c4 = 0; c4 < 14; c4++) {
            float4 v;
            upk(v.x, v.y, acc1[2 * c4]); upk(v.z, v.w, acc1[2 * c4 + 1]);
            op1[c4] = v;
        }
    }
}

extern "C" void kernel_launch(void* const* d_in, const int* in_sizes, int n_in,
                              void* d_out, int out_size) {
    const float* obs   = (const float*)d_in[0];
    const float* w1    = (const float*)d_in[1];
    const float* b1    = (const float*)d_in[2];
    const float* w2    = (const float*)d_in[3];
    const float* b2    = (const float*)d_in[4];
    const float* le    = (const float*)d_in[5];
    const float* bctl  = (const float*)d_in[6];
    const float* rctl  = (const float*)d_in[7];
    const float* bc    = (const float*)d_in[8];
    const float* ld    = (const float*)d_in[9];
    const float* rw1   = (const float*)d_in[10];
    const float* rb1   = (const float*)d_in[11];
    const float* rw2   = (const float*)d_in[12];
    const float* rb2   = (const float*)d_in[13];
    const float* rgate = (const float*)d_in[14];
    float* out = (float*)d_out;

    int B = in_sizes[0] / 14;

    prep_kernel<<<23, 256>>>(le, bctl, bc);

    void* c_addr = nullptr;
    void* s_addr = nullptr;
    cudaGetSymbolAddress(&c_addr, c_tab);
    cudaGetSymbolAddress(&s_addr, g_stage);
    cudaMemcpyAsync(c_addr, s_addr, CTAB_N * sizeof(float), cudaMemcpyDeviceToDevice, 0);

    int blocks = (B + ROWS_PER_BLOCK - 1) / ROWS_PER_BLOCK;
    rcpl_kernel<<<blocks, TPB>>>(
        obs, w1, b1, w2, b2, le, rctl, ld, rb1, rw1, rw2, rb2, rgate, out, B);
}

// round 7
// speedup vs baseline: 1.4909x; 1.4909x over previous
#include <cuda_runtime.h>
#include <math.h>

#define TPB 128
#define ROWS_PER_BLOCK 256

// ---------------- constant bank ----------------
// [0     : 8640)  emb cols 20..55  [j*36 + (c-20)]  (level0 emb || base_ctrl)
// [8640  : 8880)  kbc [j]  = bc[j] + 2*C
// [8880  : 11584) rw1 [c*52 + k]
#define EMBC_OFF 0
#define KBC_OFF  8640
#define RW1_OFF  8880
#define CTAB_N   11584
__constant__ __align__(16) float c_tab[CTAB_N];
__device__ __align__(16) float g_stage[CTAB_N];
__device__ __align__(16) float g_roots[240 * 8];

typedef unsigned long long u64;

__device__ __forceinline__ u64 pk(float x, float y) {
    u64 r; asm("mov.b64 %0,{%1,%2};" : "=l"(r) : "f"(x), "f"(y)); return r;
}
__device__ __forceinline__ void upk(float& x, float& y, u64 v) {
    asm("mov.b64 {%0,%1},%2;" : "=f"(x), "=f"(y) : "l"(v));
}
__device__ __forceinline__ u64 f2fma(u64 a, u64 b, u64 c) {
    u64 d; asm("fma.rn.f32x2 %0,%1,%2,%3;" : "=l"(d) : "l"(a), "l"(b), "l"(c)); return d;
}
__device__ __forceinline__ u64 f2mul(u64 a, u64 b) {
    u64 d; asm("mul.rn.f32x2 %0,%1,%2;" : "=l"(d) : "l"(a), "l"(b)); return d;
}
__device__ __forceinline__ u64 f2add(u64 a, u64 b) {
    u64 d; asm("add.rn.f32x2 %0,%1,%2;" : "=l"(d) : "l"(a), "l"(b)); return d;
}
__device__ __forceinline__ float ex2a(float x) {
    float y; asm("ex2.approx.ftz.f32 %0,%1;" : "=f"(y) : "f"(x)); return y;
}

// Combined prep: roots + constant-bank stage.
__global__ void prep_kernel(const float* __restrict__ le,
                            const float* __restrict__ bctl,
                            const float* __restrict__ bc,
                            const float* __restrict__ rw1) {
    const float C = 1.0201941611100342f;   // log2(e)/sqrt(2)
    int i = blockIdx.x * blockDim.x + threadIdx.x;
    if (i < 240) {
        float v[8];
#pragma unroll
        for (int k = 0; k < 8; k++) v[k] = 0.f;
        if (i < 112) {
            int p = i >> 2, sb = i & 3;
            int a = 0, rem = p;
            while (rem >= 7 - a) { rem -= (7 - a); a++; }
            int b = a + 1 + rem;
            v[a] = (sb & 2) ? -1.f : 1.f;
            v[b] = (sb & 1) ? -1.f : 1.f;
        } else {
            int b = (i - 112) << 1;
            if (__popc(b) & 1) b |= 1;
#pragma unroll
            for (int k = 0; k < 8; k++) v[k] = ((b >> k) & 1) ? -0.5f : 0.5f;
        }
#pragma unroll
        for (int k = 0; k < 8; k++) g_roots[i * 8 + k] = v[k];
    }
    if (i < CTAB_N) {
        float v;
        if (i < KBC_OFF) {
            int j = i / 36, c = i - j * 36 + 20;
            v = (c < 52) ? le[j * 52 + c] : bctl[j * 4 + (c - 52)];
        } else if (i < RW1_OFF) {
            v = bc[i - KBC_OFF] + 2.0f * C;
        } else {
            v = rw1[i - RW1_OFF];
        }
        g_stage[i] = v;
    }
}

__device__ __forceinline__ float gelu_exact(float x) {
    return 0.5f * x * (1.0f + erff(x * 0.70710678118654752f));
}

// Analytic nearest-E8-root: returns reference enumeration index, subtracts root*s in place.
__device__ __forceinline__ int decode_step(float res[8], float s) {
    float a[8];
#pragma unroll
    for (int k = 0; k < 8; k++) a[k] = fabsf(res[k]);
    int m1 = 0; float v1 = a[0];
#pragma unroll
    for (int k = 1; k < 8; k++) if (a[k] > v1) { v1 = a[k]; m1 = k; }
    int m2 = -1; float v2 = -1.f;
#pragma unroll
    for (int k = 0; k < 8; k++) if (k != m1 && a[k] > v2) { v2 = a[k]; m2 = k; }
    float valA = v1 + v2;
    float sum = 0.f;
#pragma unroll
    for (int k = 0; k < 8; k++) sum += a[k];
    int mask = 0;
#pragma unroll
    for (int k = 0; k < 8; k++) mask |= (res[k] < 0.f) ? (1 << k) : 0;
    int km = 0; float vm = a[0];
#pragma unroll
    for (int k = 1; k < 8; k++) if (a[k] < vm) { vm = a[k]; km = k; }
    int par = __popc(mask) & 1;
    float valB = 0.5f * sum - (par ? vm : 0.f);
    int idx;
    if (valA >= valB) {            // tie -> type A (lower enumeration index)
        int i = (m1 < m2) ? m1 : m2, jj = (m1 < m2) ? m2 : m1;
        int bi = (res[i] < 0.f) ? 1 : 0, bj = (res[jj] < 0.f) ? 1 : 0;
        idx = (7 * i - (i * (i - 1)) / 2 + (jj - i - 1)) * 4 + bi * 2 + bj;
        float di = bi ? -s : s, dj = bj ? -s : s;
#pragma unroll
        for (int k = 0; k < 8; k++) {
            if (k == i)  res[k] -= di;
            if (k == jj) res[k] -= dj;
        }
    } else {
        int bits = par ? (mask ^ (1 << km)) : mask;
        idx = 112 + (bits >> 1);
        float hs = 0.5f * s;
#pragma unroll
        for (int k = 0; k < 8; k++) res[k] -= ((bits >> k) & 1) ? -hs : hs;
    }
    return idx;
}

// Gated refine MLP for one row (acc[28] u64 = 56 floats, cols 0..51 refined).
// Layer-1 weights from constant bank (uniform LDC), layer-2 from smem.
__device__ __forceinline__ void refine_row(u64 acc[28],
                                           const float* rw2TS, const float* rb1S,
                                           const float* rb2S, u64 gateb) {
    u64 r2a[26];
#pragma unroll
    for (int k = 0; k < 26; k++) r2a[k] = 0ull;
#pragma unroll 2
    for (int c = 0; c < 52; c++) {
        u64 p = pk(rb1S[c], 0.f);
        const ulonglong2* wr = reinterpret_cast<const ulonglong2*>(&c_tab[RW1_OFF + c * 52]);
#pragma unroll
        for (int k = 0; k < 13; k++) {
            ulonglong2 w = wr[k];
            p = f2fma(acc[2 * k], w.x, p);
            p = f2fma(acc[2 * k + 1], w.y, p);
        }
        float pl, ph; upk(pl, ph, p);
        float gv = gelu_exact(pl + ph);
        u64 gvb = pk(gv, gv);
        const ulonglong2* w2r = reinterpret_cast<const ulonglong2*>(rw2TS + c * 52);
#pragma unroll
        for (int k = 0; k < 13; k++) {
            ulonglong2 w = w2r[k];
            r2a[2 * k]     = f2fma(gvb, w.x, r2a[2 * k]);
            r2a[2 * k + 1] = f2fma(gvb, w.y, r2a[2 * k + 1]);
        }
    }
    const u64* rb2p = reinterpret_cast<const u64*>(rb2S);
#pragma unroll
    for (int k = 0; k < 26; k++)
        acc[k] = f2fma(gateb, f2add(r2a[k], rb2p[k]), acc[k]);
}

__global__ __launch_bounds__(TPB, 3) void rcpl_kernel(
    const float* __restrict__ obs,   const float* __restrict__ w1, const float* __restrict__ b1,
    const float* __restrict__ w2,    const float* __restrict__ b2,
    const float* __restrict__ le,    const float* __restrict__ rctl,
    const float* __restrict__ ld,
    const float* __restrict__ rb1,
    const float* __restrict__ rw2,   const float* __restrict__ rb2,
    const float* __restrict__ rgate, float* __restrict__ out, int B)
{
    __shared__ __align__(16) float rootsS[1920];   // [j*8+k]
    __shared__ __align__(16) float embS20[4800];   // [j*20+c] emb cols 0..19
    __shared__ __align__(16) float rw2TS[2704];    // [c*52+k2] (transposed)
    __shared__ __align__(16) float w1S[448];       // [l*14+k]
    __shared__ __align__(16) float w2TS[256];      // [l*8+j]  (transposed)
    __shared__ float b1S[32];
    __shared__ float b2S[8];
    __shared__ __align__(16) float rb2S[52];
    __shared__ float rb1S[52];
    // ~41 KB -> 3 CTAs = 123 KB < 228 KB

    const float C = 1.0201941611100342f;   // log2(e)/sqrt(2)
    const int t = threadIdx.x;

    for (int i = t; i < 1920; i += TPB) rootsS[i] = g_roots[i];
    for (int i = t; i < 4800; i += TPB) { int j = i / 20, c = i - j * 20; embS20[i] = le[j * 52 + c]; }
    for (int i = t; i < 2704; i += TPB) { int c = i / 52, k = i - c * 52; rw2TS[i] = rw2[k * 52 + c]; }
    for (int i = t; i < 448;  i += TPB) w1S[i] = w1[i];
    for (int i = t; i < 256;  i += TPB) { int l = i >> 3, j = i & 7; w2TS[i] = w2[j * 32 + l]; }
    for (int i = t; i < 32;   i += TPB) b1S[i] = b1[i];
    for (int i = t; i < 8;    i += TPB) b2S[i] = b2[i];
    for (int i = t; i < 52;   i += TPB) { rb1S[i] = rb1[i]; rb2S[i] = rb2[i]; }
    __syncthreads();

    int r0 = blockIdx.x * ROWS_PER_BLOCK + t;
    if (r0 >= B) return;
    int r1 = r0 + TPB;
    bool has1 = (r1 < B);
    int r1c = has1 ? r1 : r0;

    // ---------------- projection: 14 -> 32 -> 8 for both rows ----------------
    float x0[14], x1[14];
    {
        const float2* p0 = reinterpret_cast<const float2*>(obs + (size_t)r0 * 14);
        const float2* p1 = reinterpret_cast<const float2*>(obs + (size_t)r1c * 14);
#pragma unroll
        for (int k = 0; k < 7; k++) {
            float2 v0 = p0[k], v1 = p1[k];
            x0[2 * k] = v0.x; x0[2 * k + 1] = v0.y;
            x1[2 * k] = v1.x; x1[2 * k + 1] = v1.y;
        }
    }
    float q0[8], q1[8];
#pragma unroll
    for (int j = 0; j < 8; j++) { q0[j] = b2S[j]; q1[j] = b2S[j]; }
#pragma unroll 2
    for (int l = 0; l < 32; l++) {
        float h0 = b1S[l], h1 = b1S[l];
        const float2* wr = reinterpret_cast<const float2*>(&w1S[l * 14]);
#pragma unroll
        for (int k = 0; k < 7; k++) {
            float2 w = wr[k];
            h0 = fmaf(x0[2 * k], w.x, h0); h0 = fmaf(x0[2 * k + 1], w.y, h0);
            h1 = fmaf(x1[2 * k], w.x, h1); h1 = fmaf(x1[2 * k + 1], w.y, h1);
        }
        float g0 = gelu_exact(h0), g1 = gelu_exact(h1);
        const float4* wt = reinterpret_cast<const float4*>(&w2TS[l * 8]);
        float4 u0 = wt[0], u1 = wt[1];
        q0[0] = fmaf(g0, u0.x, q0[0]); q0[1] = fmaf(g0, u0.y, q0[1]);
        q0[2] = fmaf(g0, u0.z, q0[2]); q0[3] = fmaf(g0, u0.w, q0[3]);
        q0[4] = fmaf(g0, u1.x, q0[4]); q0[5] = fmaf(g0, u1.y, q0[5]);
        q0[6] = fmaf(g0, u1.z, q0[6]); q0[7] = fmaf(g0, u1.w, q0[7]);
        q1[0] = fmaf(g1, u0.x, q1[0]); q1[1] = fmaf(g1, u0.y, q1[1]);
        q1[2] = fmaf(g1, u0.z, q1[2]); q1[3] = fmaf(g1, u0.w, q1[3]);
        q1[4] = fmaf(g1, u1.x, q1[4]); q1[5] = fmaf(g1, u1.y, q1[5]);
        q1[6] = fmaf(g1, u1.z, q1[6]); q1[7] = fmaf(g1, u1.w, q1[7]);
    }
    {
        float n0 = 0.f, n1 = 0.f;
#pragma unroll
        for (int j = 0; j < 8; j++) { n0 = fmaf(q0[j], q0[j], n0); n1 = fmaf(q1[j], q1[j], n1); }
        float s0 = 1.4142135623730951f / fmaxf(sqrtf(n0), 1e-12f);
        float s1 = 1.4142135623730951f / fmaxf(sqrtf(n1), 1e-12f);
#pragma unroll
        for (int j = 0; j < 8; j++) { q0[j] *= s0; q1[j] *= s1; }
    }

    u64 qp0[4], qp1[4];
#pragma unroll
    for (int k = 0; k < 4; k++) { qp0[k] = pk(q0[2 * k], q0[2 * k + 1]); qp1[k] = pk(q1[2 * k], q1[2 * k + 1]); }

    // ------- fused 240-root pass: softmax-weighted table accumulate (both rows) -------
    // Port split: cols 0..19 smem LDS | cols 20..55 const LDC. No LDG here.
    u64 acc0[28], acc1[28];
#pragma unroll
    for (int k = 0; k < 28; k++) { acc0[k] = 0ull; acc1[k] = 0ull; }
    float S0 = 0.f, S1 = 0.f;
    for (int j = 0; j < 240; j++) {
        const u64* rp = reinterpret_cast<const u64*>(&rootsS[j * 8]);
        u64 rr0 = rp[0], rr1 = rp[1], rr2 = rp[2], rr3 = rp[3];
        u64 d0 = f2mul(qp0[0], rr0);
        d0 = f2fma(qp0[1], rr1, d0); d0 = f2fma(qp0[2], rr2, d0); d0 = f2fma(qp0[3], rr3, d0);
        u64 d1 = f2mul(qp1[0], rr0);
        d1 = f2fma(qp1[1], rr1, d1); d1 = f2fma(qp1[2], rr2, d1); d1 = f2fma(qp1[3], rr3, d1);
        float dl, dh; upk(dl, dh, d0); float dot0 = dl + dh;
        float el, eh; upk(el, eh, d1); float dot1 = el + eh;
        float kbc = c_tab[KBC_OFF + j];
        float e0 = ex2a(fmaf(dot0, C, -kbc));
        float e1 = ex2a(fmaf(dot1, C, -kbc));
        S0 += e0; S1 += e1;
        u64 e0b = pk(e0, e0), e1b = pk(e1, e1);
        const ulonglong2* es = reinterpret_cast<const ulonglong2*>(&embS20[j * 20]);
#pragma unroll
        for (int k = 0; k < 5; k++) {
            ulonglong2 w = es[k];
            acc0[2 * k]     = f2fma(e0b, w.x, acc0[2 * k]);
            acc0[2 * k + 1] = f2fma(e0b, w.y, acc0[2 * k + 1]);
            acc1[2 * k]     = f2fma(e1b, w.x, acc1[2 * k]);
            acc1[2 * k + 1] = f2fma(e1b, w.y, acc1[2 * k + 1]);
        }
        const ulonglong2* ec = reinterpret_cast<const ulonglong2*>(&c_tab[EMBC_OFF + j * 36]);
#pragma unroll
        for (int k = 0; k < 9; k++) {
            ulonglong2 w = ec[k];
            acc0[10 + 2 * k]     = f2fma(e0b, w.x, acc0[10 + 2 * k]);
            acc0[10 + 2 * k + 1] = f2fma(e0b, w.y, acc0[10 + 2 * k + 1]);
            acc1[10 + 2 * k]     = f2fma(e1b, w.x, acc1[10 + 2 * k]);
            acc1[10 + 2 * k + 1] = f2fma(e1b, w.y, acc1[10 + 2 * k + 1]);
        }
    }
    {
        float i0 = 1.0f / S0, i1 = 1.0f / S1;
        u64 iv0 = pk(i0, i0), iv1 = pk(i1, i1);
#pragma unroll
        for (int k = 0; k < 28; k++) { acc0[k] = f2mul(acc0[k], iv0); acc1[k] = f2mul(acc1[k], iv1); }
    }

    // ------- residual E8 quantization: analytic decode fused with gathers -------
    float invd = expf(-ld[0]);
    {
        float res0[8], res1[8];
#pragma unroll
        for (int k = 0; k < 4; k++) {
            upk(res0[2 * k], res0[2 * k + 1], qp0[k]);
            upk(res1[2 * k], res1[2 * k + 1], qp1[k]);
        }
        float s = 2.f, gg = 1.f;
#pragma unroll
        for (int lev = 0; lev < 8; lev++) {
            int idx0 = decode_step(res0, s);
            int idx1 = decode_step(res1, s);
            if (lev > 0) {
                u64 gb = pk(gg, gg);
                const ulonglong2* e0p = reinterpret_cast<const ulonglong2*>(le + ((size_t)lev * 240 + idx0) * 52);
                const ulonglong2* e1p = reinterpret_cast<const ulonglong2*>(le + ((size_t)lev * 240 + idx1) * 52);
#pragma unroll
                for (int k = 0; k < 13; k++) {
                    ulonglong2 w0 = __ldg(&e0p[k]), w1v = __ldg(&e1p[k]);
                    acc0[2 * k]     = f2fma(gb, w0.x, acc0[2 * k]);
                    acc0[2 * k + 1] = f2fma(gb, w0.y, acc0[2 * k + 1]);
                    acc1[2 * k]     = f2fma(gb, w1v.x, acc1[2 * k]);
                    acc1[2 * k + 1] = f2fma(gb, w1v.y, acc1[2 * k + 1]);
                }
                ulonglong2 c0 = __ldg(reinterpret_cast<const ulonglong2*>(rctl + ((size_t)(lev - 1) * 240 + idx0) * 4));
                ulonglong2 c1 = __ldg(reinterpret_cast<const ulonglong2*>(rctl + ((size_t)(lev - 1) * 240 + idx1) * 4));
                acc0[26] = f2fma(gb, c0.x, acc0[26]); acc0[27] = f2fma(gb, c0.y, acc0[27]);
                acc1[26] = f2fma(gb, c1.x, acc1[26]); acc1[27] = f2fma(gb, c1.y, acc1[27]);
            }
            s *= invd; gg *= invd;
        }
    }

    // ------- stash row1 pre-refine acc to out (register relief), refine row0 -------
    float4* op1 = reinterpret_cast<float4*>(out + (size_t)r1c * 56);
    if (has1) {
#pragma unroll
        for (int c4 = 0; c4 < 14; c4++) {
            float4 v;
            upk(v.x, v.y, acc1[2 * c4]); upk(v.z, v.w, acc1[2 * c4 + 1]);
            op1[c4] = v;
        }
    }

    float gate = 1.0f / (1.0f + expf(-rgate[0]));
    u64 gateb = pk(gate, gate);

    refine_row(acc0, rw2TS, rb1S, rb2S, gateb);
    {
        float4* op = reinterpret_cast<float4*>(out + (size_t)r0 * 56);
#pragma unroll
        for (int c4 = 0; c4 < 14; c4++) {
            float4 v;
            upk(v.x, v.y, acc0[2 * c4]); upk(v.z, v.w, acc0[2 * c4 + 1]);
            op[c4] = v;
        }
    }

    if (has1) {
#pragma unroll
        for (int c4 = 0; c4 < 14; c4++) {
            float4 v = op1[c4];
            acc1[2 * c4] = pk(v.x, v.y); acc1[2 * c4 + 1] = pk(v.z, v.w);
        }
        refine_row(acc1, rw2TS, rb1S, rb2S, gateb);
#pragma unroll
        for (int c4 = 0; c4 < 14; c4++) {
            float4 v;
            upk(v.x, v.y, acc1[2 * c4]); upk(v.z, v.w, acc1[2 * c4 + 1]);
            op1[c4] = v;
        }
    }
}

extern "C" void kernel_launch(void* const* d_in, const int* in_sizes, int n_in,
                              void* d_out, int out_size) {
    const float* obs   = (const float*)d_in[0];
    const float* w1    = (const float*)d_in[1];
    const float* b1    = (const float*)d_in[2];
    const float* w2    = (const float*)d_in[3];
    const float* b2    = (const float*)d_in[4];
    const float* le    = (const float*)d_in[5];
    const float* bctl  = (const float*)d_in[6];
    const float* rctl  = (const float*)d_in[7];
    const float* bc    = (const float*)d_in[8];
    const float* ld    = (const float*)d_in[9];
    const float* rw1   = (const float*)d_in[10];
    const float* rb1   = (const float*)d_in[11];
    const float* rw2   = (const float*)d_in[12];
    const float* rb2   = (const float*)d_in[13];
    const float* rgate = (const float*)d_in[14];
    float* out = (float*)d_out;

    int B = in_sizes[0] / 14;

    prep_kernel<<<(CTAB_N + 255) / 256, 256>>>(le, bctl, bc, rw1);

    void* c_addr = nullptr;
    void* s_addr = nullptr;
    cudaGetSymbolAddress(&c_addr, c_tab);
    cudaGetSymbolAddress(&s_addr, g_stage);
    cudaMemcpyAsync(c_addr, s_addr, CTAB_N * sizeof(float), cudaMemcpyDeviceToDevice, 0);

    int blocks = (B + ROWS_PER_BLOCK - 1) / ROWS_PER_BLOCK;
    rcpl_kernel<<<blocks, TPB>>>(
        obs, w1, b1, w2, b2, le, rctl, ld, rb1, rw2, rb2, rgate, out, B);
}